// round 11
// baseline (speedup 1.0000x reference)
#include <cuda_runtime.h>
#include <cstdint>

#define SEQ_LEN  120
#define BATCH    2048
#define INPUT    6
#define HID      64
#define GATES    256
#define LAYERS   4
#define TLEN     120
#define NBC      32             // batch per cluster
#define NCTA     128            // 64 clusters x 2 CTAs
#define NTHR     256

#define CHUNK_ROWS 32
#define HHC        32                       // hh per CTA (half of HID)
#define CHUNK_F4   (CHUNK_ROWS * HHC)       // 1024 float4 = 16KB
#define CHUNK_BYTES (CHUNK_F4 * 16)
#define NSLOT      8
#define CPS        14
#define TOTALC     (240 * CPS)
#define RES_F4     (8 * HHC)                // 256 f4 = 4KB (W0, k padded to 8)
#define RES_BYTES  (RES_F4 * 16)

typedef unsigned long long ull;

// per-rank streams: [rank][CPS][32 k][32 hh] float4{wi,wf,wg,wo}
// chunk map: c0,c1 = Whh L0 k-halves; l>=1 base 2+4(l-1): Whh l (2), Wih l (2)
__device__ float4 g_stream_e[2 * CPS * CHUNK_F4];
__device__ float4 g_stream_d[2 * CPS * CHUNK_F4];
__device__ float4 g_res_e[2 * RES_F4];
__device__ float4 g_res_d[2 * RES_F4];

__global__ void lstm36206574305735_pack(
    const float* __restrict__ eW0, const float* __restrict__ eWih,
    const float* __restrict__ eWhh, const float* __restrict__ dW0,
    const float* __restrict__ dWih, const float* __restrict__ dWhh)
{
    const int PERR = CPS * CHUNK_F4 + RES_F4;        // per rank
    const int tot  = 2 * 2 * PERR;                   // phases x ranks
    for (int idx = blockIdx.x * blockDim.x + threadIdx.x; idx < tot;
         idx += gridDim.x * blockDim.x) {
        int p    = idx / (2 * PERR);
        int r2   = idx % (2 * PERR);
        int rank = r2 / PERR;
        int q    = r2 % PERR;
        const float* W0  = p ? dW0  : eW0;
        const float* Wih = p ? dWih : eWih;
        const float* Whh = p ? dWhh : eWhh;
        if (q < CPS * CHUNK_F4) {
            int c  = q / CHUNK_F4;
            int rr = q % CHUNK_F4;
            int kc = rr / HHC;
            int hh = rr % HHC;
            int u  = rank * HHC + hh;                // hidden unit
            const float* W; int k;
            if (c < 2) { W = Whh; k = c * CHUNK_ROWS + kc; }       // Whh L0
            else {
                int l = (c - 2) / 4 + 1;
                int cc = (c - 2) % 4;
                if (cc < 2) { W = Whh + (size_t)l * GATES * HID;       k = cc * CHUNK_ROWS + kc; }
                else        { W = Wih + (size_t)(l - 1) * GATES * HID; k = (cc - 2) * CHUNK_ROWS + kc; }
            }
            float4 v;
            v.x = W[(0 * HID + u) * HID + k];
            v.y = W[(1 * HID + u) * HID + k];
            v.z = W[(2 * HID + u) * HID + k];
            v.w = W[(3 * HID + u) * HID + k];
            (p ? g_stream_d : g_stream_e)[rank * CPS * CHUNK_F4 + q] = v;
        } else {
            int qq = q - CPS * CHUNK_F4;
            int k  = qq / HHC;
            int hh = qq % HHC;
            int u  = rank * HHC + hh;
            float4 v = make_float4(0.f, 0.f, 0.f, 0.f);
            if (k < INPUT) {
                v.x = W0[(0 * HID + u) * INPUT + k];
                v.y = W0[(1 * HID + u) * INPUT + k];
                v.z = W0[(2 * HID + u) * INPUT + k];
                v.w = W0[(3 * HID + u) * INPUT + k];
            }
            (p ? g_res_d : g_res_e)[rank * RES_F4 + qq] = v;
        }
    }
}

// ---- helpers ----------------------------------------------------------------
__device__ __forceinline__ void ffma2(ull& d, ull a, ull b) {
    asm("fma.rn.f32x2 %0, %1, %2, %0;" : "+l"(d) : "l"(a), "l"(b));
}
__device__ __forceinline__ ull dup2(float a) {
    ull v; asm("mov.b64 %0, {%1, %1};" : "=l"(v) : "f"(a)); return v;
}
__device__ __forceinline__ float2 unpk(ull v) {
    float2 r; asm("mov.b64 {%0, %1}, %2;" : "=f"(r.x), "=f"(r.y) : "l"(v)); return r;
}
__device__ __forceinline__ float fsig(float x) {
    return __fdividef(1.0f, 1.0f + __expf(-x));
}
__device__ __forceinline__ float ftanh_(float x) {
    return 2.0f * fsig(2.0f * x) - 1.0f;
}
__device__ __forceinline__ uint32_t smem_u32(const void* p) {
    uint32_t a;
    asm("{ .reg .u64 t; cvta.to.shared.u64 t, %1; cvt.u32.u64 %0, t; }"
        : "=r"(a) : "l"(p));
    return a;
}
__device__ __forceinline__ void wait_parity(uint32_t mb, uint32_t parity) {
    asm volatile(
        "{\n\t"
        ".reg .pred P;\n\t"
        "WLOOP_%=:\n\t"
        "mbarrier.try_wait.parity.acquire.cta.shared::cta.b64 P, [%0], %1, 0x989680;\n\t"
        "@P bra WDONE_%=;\n\t"
        "bra WLOOP_%=;\n\t"
        "WDONE_%=:\n\t"
        "}"
        :: "r"(mb), "r"(parity) : "memory");
}
__device__ __forceinline__ void wait_parity_cl(uint32_t mb, uint32_t parity) {
    asm volatile(
        "{\n\t"
        ".reg .pred P;\n\t"
        "WLOOP_%=:\n\t"
        "mbarrier.try_wait.parity.acquire.cluster.shared::cta.b64 P, [%0], %1, 0x989680;\n\t"
        "@P bra WDONE_%=;\n\t"
        "bra WLOOP_%=;\n\t"
        "WDONE_%=:\n\t"
        "}"
        :: "r"(mb), "r"(parity) : "memory");
}

// gemv, stride-32 batch rows: per k = 2 LDS.128 + 4 dup MOVs + 8 FFMA2
template <int K>
__device__ __forceinline__ void gemv_s(const float4* __restrict__ wslot,
                                       const float* __restrict__ hs,
                                       int hh, int bg, ull acc[8])
{
#pragma unroll 8
    for (int k = 0; k < K; k++) {
        float4 w4 = wslot[k * HHC + hh];
        ulonglong2 hv = *(const ulonglong2*)(hs + k * NBC + bg * 4);
        ull wi = dup2(w4.x), wf = dup2(w4.y), wg = dup2(w4.z), wo = dup2(w4.w);
        ffma2(acc[0], wi, hv.x); ffma2(acc[1], wi, hv.y);
        ffma2(acc[2], wf, hv.x); ffma2(acc[3], wf, hv.y);
        ffma2(acc[4], wg, hv.x); ffma2(acc[5], wg, hv.y);
        ffma2(acc[6], wo, hv.x); ffma2(acc[7], wo, hv.y);
    }
}

// ---- smem layout ------------------------------------------------------------
#define RING_SZ   (NSLOT * CHUNK_BYTES)     // 131072
#define RES_OFF   RING_SZ                   // +4096
#define MBAR_B    (RES_OFF + RES_BYTES)     // 135168: 8 ring, rmb, 4 exch
#define RMB_OFF   (MBAR_B + NSLOT * 8)      // +64
#define EXCH_OFF  (RMB_OFF + 8)             // +72 .. +96
#define FB_B      (MBAR_B + 128)            // 135296
#define HD_F      0                          // [2 buf][4 l][64 u][32 b]
#define SZ_HD     (2 * LAYERS * HID * NBC)   // 16384 floats
#define IND_F     (HD_F + SZ_HD)             // [8 k][32 b], rows 6,7 zero
#define SZ_IND    (8 * NBC)
#define LW_F      (IND_F + SZ_IND)
#define LB_F      (LW_F + HID * INPUT)
#define BIAS_F    (LB_F + 8)                 // ull[2][4][32 hh][4 g] = 2048 floats
#define SZ_BIAS   (2 * LAYERS * HHC * 8)
#define SMEM_TOTAL_B (FB_B + (BIAS_F + SZ_BIAS) * 4)

__global__ void __launch_bounds__(NTHR, 1) __cluster_dims__(2, 1, 1)
lstm36206574305735_main(const float* __restrict__ x,
                        const float* __restrict__ eB,
                        const float* __restrict__ dB,
                        const float* __restrict__ linW,
                        const float* __restrict__ linB,
                        float* __restrict__ out)
{
    extern __shared__ char sm[];
    const uint32_t base_u = smem_u32(sm);
    float* fb   = (float*)(sm + FB_B);
    float* hd   = fb + HD_F;
    float* ind  = fb + IND_F;
    float* lw_s = fb + LW_F;
    float* lb_s = fb + LB_F;
    ull*   bias = (ull*)(fb + BIAS_F);

    const int tid = threadIdx.x;
    const int hh  = tid >> 3;       // 0..31 local hidden unit
    const int bg  = tid & 7;        // batch quad (4 batch each, NBC=32)
    uint32_t rank;
    asm("mov.u32 %0, %%cluster_ctarank;" : "=r"(rank));
    const int hh_g = (int)rank * HHC + hh;
    const int b0c  = (blockIdx.x >> 1) * NBC;   // cluster batch base

    uint32_t peer_u;
    asm("mapa.shared::cluster.u32 %0, %1, %2;" : "=r"(peer_u)
        : "r"(base_u), "r"(rank ^ 1u));

    auto issue_one = [&](int G) {
        if (G >= TOTALC) return;
        int s = G % NSLOT;
        int cc = G % CPS;
        const float4* src = (G < 120 * CPS ? g_stream_e : g_stream_d)
                            + (size_t)rank * CPS * CHUNK_F4 + (size_t)cc * CHUNK_F4;
        uint32_t mb = base_u + MBAR_B + s * 8;
        asm volatile("mbarrier.arrive.expect_tx.shared.b64 _, [%0], %1;"
                     :: "r"(mb), "r"((uint32_t)CHUNK_BYTES) : "memory");
        asm volatile("cp.async.bulk.shared::cluster.global.mbarrier::complete_tx::bytes "
                     "[%0], [%1], %2, [%3];"
                     :: "r"(base_u + (uint32_t)s * CHUNK_BYTES), "l"(src),
                        "r"((uint32_t)CHUNK_BYTES), "r"(mb) : "memory");
    };
    auto issue_res = [&](int p) {
        const float4* src = (p ? g_res_d : g_res_e) + (size_t)rank * RES_F4;
        asm volatile("mbarrier.arrive.expect_tx.shared.b64 _, [%0], %1;"
                     :: "r"(base_u + RMB_OFF), "r"((uint32_t)RES_BYTES) : "memory");
        asm volatile("cp.async.bulk.shared::cluster.global.mbarrier::complete_tx::bytes "
                     "[%0], [%1], %2, [%3];"
                     :: "r"(base_u + (uint32_t)RES_OFF), "l"(src),
                        "r"((uint32_t)RES_BYTES), "r"(base_u + RMB_OFF) : "memory");
    };
    auto lw = [&](int G) {
        if (G >= TOTALC) return;
        wait_parity(base_u + MBAR_B + (G % NSLOT) * 8, (uint32_t)((G >> 3) & 1));
    };

    if (tid == 0) {
        for (int s = 0; s < NSLOT; s++)
            asm volatile("mbarrier.init.shared.b64 [%0], 1;"
                         :: "r"(base_u + MBAR_B + s * 8) : "memory");
        asm volatile("mbarrier.init.shared.b64 [%0], 1;"
                     :: "r"(base_u + RMB_OFF) : "memory");
        for (int l = 0; l < LAYERS; l++)
            asm volatile("mbarrier.init.shared.b64 [%0], %1;"
                         :: "r"(base_u + EXCH_OFF + l * 8), "r"((uint32_t)NTHR) : "memory");
        asm volatile("fence.proxy.async.shared::cta;" ::: "memory");
        issue_res(0);
        for (int g = 0; g < NSLOT; g++) issue_one(g);
    }

    for (int i = tid; i < SZ_HD; i += NTHR) hd[i] = 0.0f;
    for (int i = tid; i < SZ_IND; i += NTHR) ind[i] = 0.0f;
    for (int i = tid; i < HID * INPUT; i += NTHR) {
        int h2 = i / INPUT, ii2 = i % INPUT;
        lw_s[h2 * INPUT + ii2] = linW[ii2 * HID + h2];
    }
    if (tid < INPUT) lb_s[tid] = linB[tid];
    for (int u = tid; u < 2 * LAYERS * HHC; u += NTHR) {
        int phase = u >> 7, l = (u >> 5) & 3, hx = u & 31;
        int ug = (int)rank * HHC + hx;
        const float* B = phase ? dB : eB;
        bias[u * 4 + 0] = dup2(B[l * GATES + ug]);
        bias[u * 4 + 1] = dup2(B[l * GATES + HID + ug]);
        bias[u * 4 + 2] = dup2(B[l * GATES + 2 * HID + ug]);
        bias[u * 4 + 3] = dup2(B[l * GATES + 3 * HID + ug]);
    }
    __syncthreads();
    // all mbarriers init'd in both CTAs before any cross-CTA traffic
    asm volatile("barrier.cluster.arrive.aligned;" ::: "memory");
    asm volatile("barrier.cluster.wait.aligned;" ::: "memory");

    float c_reg[LAYERS][4];
#pragma unroll
    for (int l = 0; l < LAYERS; l++)
#pragma unroll
        for (int bi = 0; bi < 4; bi++) c_reg[l][bi] = 0.0f;

    const int  bb  = tid / INPUT;           // 0..31 (tid<192)
    const int  ii  = tid % INPUT;
    const bool isx = tid < INPUT * NBC;     // 192 threads
    float xreg = 0.0f;
    if (isx) xreg = x[(size_t)(b0c + bb) * INPUT + ii];

    if (tid == 0) { wait_parity(base_u + RMB_OFF, 0); lw(0); lw(1); }
    __syncthreads();

    auto slotp = [&](int G) -> const float4* {
        return (const float4*)(sm + (size_t)(G % NSLOT) * CHUNK_BYTES);
    };
    auto initb = [&](int p, int l, ull acc[8]) {
        const ull* bv = bias + ((p * LAYERS + l) * HHC + hh) * 4;
        acc[0] = acc[1] = bv[0];
        acc[2] = acc[3] = bv[1];
        acc[4] = acc[5] = bv[2];
        acc[6] = acc[7] = bv[3];
    };
    // epilogue: cell update, write my hh_g row to BOTH CTAs' h[buf w][l], arrive peer
    auto epi = [&](int l, int w, ull acc[8]) {
        float2 ai0 = unpk(acc[0]), ai1 = unpk(acc[1]);
        float2 af0 = unpk(acc[2]), af1 = unpk(acc[3]);
        float2 ag0 = unpk(acc[4]), ag1 = unpk(acc[5]);
        float2 ao0 = unpk(acc[6]), ao1 = unpk(acc[7]);
        float ai[4] = {ai0.x, ai0.y, ai1.x, ai1.y};
        float af[4] = {af0.x, af0.y, af1.x, af1.y};
        float ag[4] = {ag0.x, ag0.y, ag1.x, ag1.y};
        float ao[4] = {ao0.x, ao0.y, ao1.x, ao1.y};
        float hout[4];
#pragma unroll
        for (int bi = 0; bi < 4; bi++) {
            float c = fmaf(fsig(af[bi]), c_reg[l][bi],
                           fsig(ai[bi]) * ftanh_(ag[bi]));
            c_reg[l][bi] = c;
            hout[bi] = fsig(ao[bi]) * ftanh_(c);
        }
        uint32_t foff = (uint32_t)((HD_F + ((w * LAYERS + l) * HID + hh_g) * NBC
                                    + bg * 4) * 4) + FB_B;
        *(float4*)(sm + foff) = make_float4(hout[0], hout[1], hout[2], hout[3]);
        asm volatile("st.shared::cluster.v4.f32 [%0], {%1, %2, %3, %4};"
                     :: "r"(peer_u + foff),
                        "f"(hout[0]), "f"(hout[1]), "f"(hout[2]), "f"(hout[3])
                     : "memory");
        asm volatile("fence.acq_rel.cluster;" ::: "memory");
        asm volatile("mbarrier.arrive.shared::cluster.b64 _, [%0];"
                     :: "r"(peer_u + EXCH_OFF + (uint32_t)l * 8) : "memory");
    };
    auto wexch = [&](int l, int t) {
        wait_parity_cl(base_u + EXCH_OFF + l * 8, (uint32_t)(t & 1));
    };

    int G = 0;
    for (int t = 0; t < SEQ_LEN + TLEN; t++) {
        const bool dec = (t >= SEQ_LEN);
        const int  p   = dec ? 1 : 0;
        const int  w   = t & 1;             // write buffer
        const int  ow  = w ^ 1;             // old-h buffer
        if (!dec && isx) {
            ind[ii * NBC + bb] = xreg;
            if (t + 1 < SEQ_LEN)
                xreg = x[((size_t)(t + 1) * BATCH + b0c + bb) * INPUT + ii];
        }

        ull acc[8];
        float* hO = hd + (ow * LAYERS) * HID * NBC;   // old buffer base
        float* hN = hd + (w  * LAYERS) * HID * NBC;   // new buffer base
        const int LSZ = HID * NBC;                     // 2048 floats per layer

        // S0: Whh L0 over old h0
        initb(p, 0, acc);
        gemv_s<32>(slotp(G + 0), hO,        hh, bg, acc);
        gemv_s<32>(slotp(G + 1), hO + 1024, hh, bg, acc);
        __syncthreads();
        if (tid == 0) { issue_one(G + 8); issue_one(G + 9); }

        // S1: W0 (resident) over ind + epi0
        gemv_s<8>((const float4*)(sm + RES_OFF), ind, hh, bg, acc);
        epi(0, w, acc);
        if (tid == 0) { lw(G + 2); lw(G + 3); }
        __syncthreads();
        if (tid == 0 && t == SEQ_LEN - 1) issue_res(1);

        // S2: Whh L1 over old h1
        initb(p, 1, acc);
        gemv_s<32>(slotp(G + 2), hO + LSZ,        hh, bg, acc);
        gemv_s<32>(slotp(G + 3), hO + LSZ + 1024, hh, bg, acc);
        if (tid == 0) { lw(G + 4); lw(G + 5); wexch(0, t); }
        __syncthreads();
        if (tid == 0) { issue_one(G + 10); issue_one(G + 11); }

        // S3: Wih L1 over new h0 + epi1
        gemv_s<32>(slotp(G + 4), hN,        hh, bg, acc);
        gemv_s<32>(slotp(G + 5), hN + 1024, hh, bg, acc);
        epi(1, w, acc);
        if (tid == 0) { lw(G + 6); lw(G + 7); }
        __syncthreads();
        if (tid == 0) { issue_one(G + 12); issue_one(G + 13); }

        // S4: Whh L2 over old h2
        initb(p, 2, acc);
        gemv_s<32>(slotp(G + 6), hO + 2 * LSZ,        hh, bg, acc);
        gemv_s<32>(slotp(G + 7), hO + 2 * LSZ + 1024, hh, bg, acc);
        if (tid == 0) { lw(G + 8); lw(G + 9); wexch(1, t); }
        __syncthreads();
        if (tid == 0) { issue_one(G + 14); issue_one(G + 15); }

        // S5: Wih L2 over new h1 + epi2
        gemv_s<32>(slotp(G + 8), hN + LSZ,        hh, bg, acc);
        gemv_s<32>(slotp(G + 9), hN + LSZ + 1024, hh, bg, acc);
        epi(2, w, acc);
        if (tid == 0) { lw(G + 10); lw(G + 11); }
        __syncthreads();
        if (tid == 0) { issue_one(G + 16); issue_one(G + 17); }

        // S6: Whh L3 over old h3
        initb(p, 3, acc);
        gemv_s<32>(slotp(G + 10), hO + 3 * LSZ,        hh, bg, acc);
        gemv_s<32>(slotp(G + 11), hO + 3 * LSZ + 1024, hh, bg, acc);
        if (tid == 0) { lw(G + 12); lw(G + 13); wexch(2, t); }
        __syncthreads();
        if (tid == 0) { issue_one(G + 18); issue_one(G + 19); }

        // S7: Wih L3 over new h2 + epi3
        gemv_s<32>(slotp(G + 12), hN + 2 * LSZ,        hh, bg, acc);
        gemv_s<32>(slotp(G + 13), hN + 2 * LSZ + 1024, hh, bg, acc);
        epi(3, w, acc);
        if (tid == 0) {
            lw(G + 14); lw(G + 15);           // next step's c0,c1
            wexch(3, t);                      // full h3 (both halves) arrived
            if (t == SEQ_LEN - 1) wait_parity(base_u + RMB_OFF, 1);
        }
        __syncthreads();
        if (tid == 0) { issue_one(G + 20); issue_one(G + 21); }

        if (dec && isx) {
            const float* htop = hN + 3 * LSZ;
            float v = lb_s[ii];
#pragma unroll 8
            for (int h4 = 0; h4 < HID; h4++)
                v += lw_s[h4 * INPUT + ii] * htop[h4 * NBC + bb];
            if ((bb >> 4) == (int)rank)       // split gmem writes by rank
                out[((size_t)(t - SEQ_LEN) * BATCH + b0c + bb) * INPUT + ii] = v;
            ind[ii * NBC + bb] = v;           // full feedback, both CTAs
        }
        // ind consumed at next step's S1, after S0's __syncthreads

        G += CPS;
    }

    asm volatile("barrier.cluster.arrive.aligned;" ::: "memory");
    asm volatile("barrier.cluster.wait.aligned;" ::: "memory");
}

extern "C" void kernel_launch(void* const* d_in, const int* in_sizes, int n_in,
                              void* d_out, int out_size)
{
    const float* x    = (const float*)d_in[0];
    const float* eW0  = (const float*)d_in[1];
    const float* eWih = (const float*)d_in[2];
    const float* eWhh = (const float*)d_in[3];
    const float* eB   = (const float*)d_in[4];
    const float* dW0  = (const float*)d_in[5];
    const float* dWih = (const float*)d_in[6];
    const float* dWhh = (const float*)d_in[7];
    const float* dB   = (const float*)d_in[8];
    const float* linW = (const float*)d_in[9];
    const float* linB = (const float*)d_in[10];
    float* out = (float*)d_out;

    lstm36206574305735_pack<<<230, 256>>>(eW0, eWih, eWhh, dW0, dWih, dWhh);

    cudaFuncSetAttribute(lstm36206574305735_main,
                         cudaFuncAttributeMaxDynamicSharedMemorySize, SMEM_TOTAL_B);
    lstm36206574305735_main<<<NCTA, NTHR, SMEM_TOTAL_B>>>(x, eB, dB, linW, linB, out);
}

// round 12
// speedup vs baseline: 1.7968x; 1.7968x over previous
#include <cuda_runtime.h>
#include <cstdint>

#define SEQ_LEN  120
#define BATCH    2048
#define INPUT    6
#define HID      64
#define GATES    256
#define LAYERS   4
#define TLEN     120
#define NB       16
#define NCTA     (BATCH / NB)   // 128
#define NTHR     256

#define UNIT_F4     4096                 // 64 k x 64 hh float4 = 64KB
#define UNIT_BYTES  (UNIT_F4 * 16)
#define NBUF        3
#define UPS         7                    // units per step
#define UNITS_TOTAL (240 * UPS)          // 1680
#define RES_F4      512                  // W0: 8 k x 64 hh = 8KB
#define RES_BYTES   (RES_F4 * 16)

typedef unsigned long long ull;

// per-phase periodic stream: [7 units][64 k][64 hh] float4 {wi,wf,wg,wo}
// unit map: u0=Whh L0; u1=Whh L1; u2=Wih L1; u3=Whh L2; u4=Wih L2; u5=Whh L3; u6=Wih L3
__device__ float4 g_stream_e[UPS * UNIT_F4];
__device__ float4 g_stream_d[UPS * UNIT_F4];
__device__ float4 g_res_e[RES_F4];
__device__ float4 g_res_d[RES_F4];

__global__ void lstm36206574305735_pack(
    const float* __restrict__ eW0, const float* __restrict__ eWih,
    const float* __restrict__ eWhh, const float* __restrict__ dW0,
    const float* __restrict__ dWih, const float* __restrict__ dWhh)
{
    const int PER = UPS * UNIT_F4 + RES_F4;
    const int tot = 2 * PER;
    for (int idx = blockIdx.x * blockDim.x + threadIdx.x; idx < tot;
         idx += gridDim.x * blockDim.x) {
        int p = idx / PER;
        int r = idx % PER;
        const float* W0  = p ? dW0  : eW0;
        const float* Wih = p ? dWih : eWih;
        const float* Whh = p ? dWhh : eWhh;
        if (r < UPS * UNIT_F4) {
            int su = r / UNIT_F4;
            int rr = r % UNIT_F4;
            int k  = rr / HID;
            int hh = rr % HID;
            const float* W;
            if (su == 0)          W = Whh;                                  // Whh L0
            else if (su & 1)      W = Whh + (size_t)((su + 1) / 2) * GATES * HID;
            else                  W = Wih + (size_t)(su / 2 - 1) * GATES * HID;
            float4 v;
            v.x = W[(0 * HID + hh) * HID + k];
            v.y = W[(1 * HID + hh) * HID + k];
            v.z = W[(2 * HID + hh) * HID + k];
            v.w = W[(3 * HID + hh) * HID + k];
            (p ? g_stream_d : g_stream_e)[r] = v;
        } else {
            int q  = r - UPS * UNIT_F4;
            int k  = q / HID;
            int hh = q % HID;
            float4 v = make_float4(0.f, 0.f, 0.f, 0.f);
            if (k < INPUT) {
                v.x = W0[(0 * HID + hh) * INPUT + k];
                v.y = W0[(1 * HID + hh) * INPUT + k];
                v.z = W0[(2 * HID + hh) * INPUT + k];
                v.w = W0[(3 * HID + hh) * INPUT + k];
            }
            (p ? g_res_d : g_res_e)[q] = v;
        }
    }
}

// ---- helpers ----------------------------------------------------------------
__device__ __forceinline__ void ffma2(ull& d, ull a, ull b) {
    asm("fma.rn.f32x2 %0, %1, %2, %0;" : "+l"(d) : "l"(a), "l"(b));
}
__device__ __forceinline__ ull dup2(float a) {
    ull v; asm("mov.b64 %0, {%1, %1};" : "=l"(v) : "f"(a)); return v;
}
__device__ __forceinline__ float2 unpk(ull v) {
    float2 r; asm("mov.b64 {%0, %1}, %2;" : "=f"(r.x), "=f"(r.y) : "l"(v)); return r;
}
__device__ __forceinline__ float fsig(float x) {
    return __fdividef(1.0f, 1.0f + __expf(-x));
}
__device__ __forceinline__ float ftanh_(float x) {
    return 2.0f * fsig(2.0f * x) - 1.0f;
}
__device__ __forceinline__ uint32_t smem_u32(const void* p) {
    uint32_t a;
    asm("{ .reg .u64 t; cvta.to.shared.u64 t, %1; cvt.u32.u64 %0, t; }"
        : "=r"(a) : "l"(p));
    return a;
}
__device__ __forceinline__ void cpa16(uint32_t dst, const void* src) {
    asm volatile("cp.async.cg.shared.global [%0], [%1], 16;"
                 :: "r"(dst), "l"(src) : "memory");
}
#define CPA_COMMIT() asm volatile("cp.async.commit_group;" ::: "memory")
#define CPA_WAIT1()  asm volatile("cp.async.wait_group 1;" ::: "memory")

// proven gemv mix: per k = 2 LDS.128 + 4 dup MOVs + 8 FFMA2
template <int K>
__device__ __forceinline__ void gemv_s(const float4* __restrict__ wslot,
                                       const float* __restrict__ hs,
                                       int hh, int bg, ull acc[8])
{
#pragma unroll 8
    for (int k = 0; k < K; k++) {
        float4 w4 = wslot[k * HID + hh];
        ulonglong2 hv = *(const ulonglong2*)(hs + k * 16 + bg * 4);
        ull wi = dup2(w4.x), wf = dup2(w4.y), wg = dup2(w4.z), wo = dup2(w4.w);
        ffma2(acc[0], wi, hv.x); ffma2(acc[1], wi, hv.y);
        ffma2(acc[2], wf, hv.x); ffma2(acc[3], wf, hv.y);
        ffma2(acc[4], wg, hv.x); ffma2(acc[5], wg, hv.y);
        ffma2(acc[6], wo, hv.x); ffma2(acc[7], wo, hv.y);
    }
}

// ---- smem layout (bytes) ------------------------------------------------------
#define BUFS_B   0
#define BUFS_SZ  (NBUF * UNIT_BYTES)      // 196608
#define RES_B    BUFS_SZ                  // +8192
#define FB_B     (RES_B + RES_BYTES)      // 204800
// floats from FB_B
#define HD_F     0                         // [4][64][16]
#define SZ_HD    (LAYERS * HID * 16)       // 4096
#define IND_F    (HD_F + SZ_HD)            // [8][16], rows 6,7 zero
#define SZ_IND   (8 * 16)
#define LW_F     (IND_F + SZ_IND)
#define LB_F     (LW_F + HID * INPUT)
#define BIAS_F   (LB_F + 8)                // float4[2][4][64] = 2048 floats
#define SZ_BIAS  (2 * LAYERS * HID * 4)
#define SMEM_TOTAL_B (FB_B + (BIAS_F + SZ_BIAS) * 4)   // 231456

__global__ void __launch_bounds__(NTHR, 1)
lstm36206574305735_main(const float* __restrict__ x,
                        const float* __restrict__ eB,
                        const float* __restrict__ dB,
                        const float* __restrict__ linW,
                        const float* __restrict__ linB,
                        float* __restrict__ out)
{
    extern __shared__ char sm[];
    const uint32_t base_u = smem_u32(sm);
    float* fb   = (float*)(sm + FB_B);
    float* hd   = fb + HD_F;
    float* ind  = fb + IND_F;
    float* lw_s = fb + LW_F;
    float* lb_s = fb + LB_F;
    float4* bias = (float4*)(fb + BIAS_F);

    const int tid = threadIdx.x;
    const int hh  = tid >> 2;
    const int bg  = tid & 3;
    const int b0  = blockIdx.x * NB;

    // ---- cp.async streamers ----
    auto issue_unit = [&](int u) {
        if (u < UNITS_TOTAL) {
            const float4* src = (u < 120 * UPS ? g_stream_e : g_stream_d)
                                + (size_t)(u % UPS) * UNIT_F4;
            uint32_t dst = base_u + (uint32_t)(u % NBUF) * UNIT_BYTES + tid * 16;
#pragma unroll
            for (int j = 0; j < 16; j++)
                cpa16(dst + j * 4096, src + tid + j * 256);
        }
    };
    auto issue_res = [&](int p) {
        const float4* src = (p ? g_res_d : g_res_e);
        uint32_t dst = base_u + (uint32_t)RES_B + tid * 16;
        cpa16(dst,        src + tid);
        cpa16(dst + 4096, src + tid + 256);
    };
    auto bufp = [&](int u) -> const float4* {
        return (const float4*)(sm + (size_t)(u % NBUF) * UNIT_BYTES);
    };

    // ---- init smem data ----
    for (int i = tid; i < SZ_HD; i += NTHR) hd[i] = 0.0f;
    for (int i = tid; i < SZ_IND; i += NTHR) ind[i] = 0.0f;
    for (int i = tid; i < HID * INPUT; i += NTHR) {
        int h2 = i / INPUT, ii2 = i % INPUT;
        lw_s[h2 * INPUT + ii2] = linW[ii2 * HID + h2];
    }
    if (tid < INPUT) lb_s[tid] = linB[tid];
    for (int u = tid; u < 2 * LAYERS * HID; u += NTHR) {
        int phase = u >> 8, l = (u >> 6) & 3, hx = u & 63;
        const float* B = phase ? dB : eB;
        bias[u] = make_float4(B[l * GATES + hx],
                              B[l * GATES + HID + hx],
                              B[l * GATES + 2 * HID + hx],
                              B[l * GATES + 3 * HID + hx]);
    }

    // prefetch: group1 = res + unit0, group2 = unit1
    issue_res(0);
    issue_unit(0);
    CPA_COMMIT();
    issue_unit(1);
    CPA_COMMIT();
    CPA_WAIT1();          // res + unit0 complete
    __syncthreads();

    float c_reg[LAYERS][4];
#pragma unroll
    for (int l = 0; l < LAYERS; l++)
#pragma unroll
        for (int bi = 0; bi < 4; bi++) c_reg[l][bi] = 0.0f;

    const int  bb  = tid / INPUT;
    const int  ii  = tid % INPUT;
    const bool isx = tid < INPUT * NB;
    float xreg = 0.0f;
    if (isx) xreg = x[(size_t)(b0 + bb) * INPUT + ii];

    auto initb = [&](int p, int l, ull acc[8]) {
        float4 bv = bias[(p * LAYERS + l) * HID + hh];
        acc[0] = acc[1] = dup2(bv.x);
        acc[2] = acc[3] = dup2(bv.y);
        acc[4] = acc[5] = dup2(bv.z);
        acc[6] = acc[7] = dup2(bv.w);
    };
    auto epi = [&](int l, ull acc[8]) {
        float2 ai0 = unpk(acc[0]), ai1 = unpk(acc[1]);
        float2 af0 = unpk(acc[2]), af1 = unpk(acc[3]);
        float2 ag0 = unpk(acc[4]), ag1 = unpk(acc[5]);
        float2 ao0 = unpk(acc[6]), ao1 = unpk(acc[7]);
        float ai[4] = {ai0.x, ai0.y, ai1.x, ai1.y};
        float af[4] = {af0.x, af0.y, af1.x, af1.y};
        float ag[4] = {ag0.x, ag0.y, ag1.x, ag1.y};
        float ao[4] = {ao0.x, ao0.y, ao1.x, ao1.y};
        float hout[4];
#pragma unroll
        for (int bi = 0; bi < 4; bi++) {
            float c = fmaf(fsig(af[bi]), c_reg[l][bi],
                           fsig(ai[bi]) * ftanh_(ag[bi]));
            c_reg[l][bi] = c;
            hout[bi] = fsig(ao[bi]) * ftanh_(c);
        }
        float* hrow = hd + (l * HID + hh) * 16 + bg * 4;
        *(float4*)hrow = make_float4(hout[0], hout[1], hout[2], hout[3]);
    };
    // close a segment: prefetch unit u+2, guarantee u+1 resident, sync
    auto seg_tail = [&](int u, bool res_reload) {
        issue_unit(u + 2);
        if (res_reload) issue_res(1);   // bundled into this commit group
        CPA_COMMIT();
        CPA_WAIT1();
        __syncthreads();
    };

    int u = 0;
    for (int t = 0; t < SEQ_LEN + TLEN; t++) {
        const int p = (t >= SEQ_LEN) ? 1 : 0;

        // ---- S0: [proj(t-1) / ind load] + Whh L0 ----
        if (isx) {
            if (t > SEQ_LEN) {
                const float* htop = hd + 3 * 1024;
                float v = lb_s[ii];
#pragma unroll 8
                for (int h4 = 0; h4 < HID; h4++)
                    v += lw_s[h4 * INPUT + ii] * htop[h4 * 16 + bb];
                out[((size_t)(t - 1 - SEQ_LEN) * BATCH + b0 + bb) * INPUT + ii] = v;
                ind[ii * 16 + bb] = v;
            } else if (t < SEQ_LEN) {
                ind[ii * 16 + bb] = xreg;
                if (t + 1 < SEQ_LEN)
                    xreg = x[((size_t)(t + 1) * BATCH + b0 + bb) * INPUT + ii];
            }
        }
        ull acc[8];
        initb(p, 0, acc);
        gemv_s<64>(bufp(u), hd, hh, bg, acc);
        seg_tail(u, false); u++;

        // ---- S1: W0(res) + epi0 ; Whh L1 ----
        gemv_s<8>((const float4*)(sm + RES_B), ind, hh, bg, acc);
        epi(0, acc);
        initb(p, 1, acc);
        gemv_s<64>(bufp(u), hd + 1024, hh, bg, acc);
        seg_tail(u, false); u++;

        // ---- S2: Wih L1 over new h0 + epi1 ----
        gemv_s<64>(bufp(u), hd, hh, bg, acc);
        epi(1, acc);
        seg_tail(u, t == SEQ_LEN - 1); u++;   // reload decoder W0 here

        // ---- S3: Whh L2 ----
        initb(p, 2, acc);
        gemv_s<64>(bufp(u), hd + 2 * 1024, hh, bg, acc);
        seg_tail(u, false); u++;

        // ---- S4: Wih L2 over new h1 + epi2 ----
        gemv_s<64>(bufp(u), hd + 1024, hh, bg, acc);
        epi(2, acc);
        seg_tail(u, false); u++;

        // ---- S5: Whh L3 ----
        initb(p, 3, acc);
        gemv_s<64>(bufp(u), hd + 3 * 1024, hh, bg, acc);
        seg_tail(u, false); u++;

        // ---- S6: Wih L3 over new h2 + epi3 ----
        gemv_s<64>(bufp(u), hd + 2 * 1024, hh, bg, acc);
        epi(3, acc);
        seg_tail(u, false); u++;
    }

    // tail: projection for the final decoder step (t = 239)
    if (isx) {
        const float* htop = hd + 3 * 1024;
        float v = lb_s[ii];
#pragma unroll 8
        for (int h4 = 0; h4 < HID; h4++)
            v += lw_s[h4 * INPUT + ii] * htop[h4 * 16 + bb];
        out[((size_t)(TLEN - 1) * BATCH + b0 + bb) * INPUT + ii] = v;
    }
}

extern "C" void kernel_launch(void* const* d_in, const int* in_sizes, int n_in,
                              void* d_out, int out_size)
{
    const float* x    = (const float*)d_in[0];
    const float* eW0  = (const float*)d_in[1];
    const float* eWih = (const float*)d_in[2];
    const float* eWhh = (const float*)d_in[3];
    const float* eB   = (const float*)d_in[4];
    const float* dW0  = (const float*)d_in[5];
    const float* dWih = (const float*)d_in[6];
    const float* dWhh = (const float*)d_in[7];
    const float* dB   = (const float*)d_in[8];
    const float* linW = (const float*)d_in[9];
    const float* linB = (const float*)d_in[10];
    float* out = (float*)d_out;

    lstm36206574305735_pack<<<228, 256>>>(eW0, eWih, eWhh, dW0, dWih, dWhh);

    cudaFuncSetAttribute(lstm36206574305735_main,
                         cudaFuncAttributeMaxDynamicSharedMemorySize, SMEM_TOTAL_B);
    lstm36206574305735_main<<<NCTA, NTHR, SMEM_TOTAL_B>>>(x, eB, dB, linW, linB, out);
}